// round 12
// baseline (speedup 1.0000x reference)
#include <cuda_runtime.h>

// Problem constants
#define PP      128                 // polygons
#define NN      128                 // pred points per polygon per level
#define MM      1024                // gt points per polygon
#define CHUNKS  8
#define CM      (MM/CHUNKS)         // 128 gt points per chunk
#define LVL_STRIDE (PP*NN)          // 16384

// level weights / (3 * P * N)
#define W0 (0.2f/49152.0f)
#define W1 (0.3f/49152.0f)
#define W2 (0.5f/49152.0f)

typedef unsigned long long u64;

// Scratch (no allocations allowed)
__device__ float    g_partial[CHUNKS][3 * LVL_STRIDE];
__device__ float    g_poly[PP];
__device__ unsigned g_cnt[PP];      // per-polygon tickets (zero-init; combiner resets)
__device__ unsigned g_cnt2;         // global ticket (zero-init; winner resets)

// ---- packed f32x2 helpers (sm_103a). fma2 is pure (non-volatile): schedulable. ----
__device__ __forceinline__ u64 pack2(float x) {
    u64 r; asm("mov.b64 %0, {%1, %1};" : "=l"(r) : "f"(x)); return r;
}
__device__ __forceinline__ u64 fma2(u64 a, u64 b, u64 c) {
    u64 d; asm("fma.rn.f32x2 %0, %1, %2, %3;" : "=l"(d) : "l"(a), "l"(b), "l"(c)); return d;
}
__device__ __forceinline__ void min2acc(float& m0, float& m1, u64 t) {
    float2 f = *reinterpret_cast<float2*>(&t);
    m0 = fminf(m0, f.x);
    m1 = fminf(m1, f.y);
}
// Scoped acq_rel atomic ticket: NO MEMBAR.GPU (the R2/R5 poison).
__device__ __forceinline__ unsigned atom_ticket(unsigned* p) {
    unsigned old;
    asm volatile("atom.acq_rel.gpu.global.add.u32 %0, [%1], 1;"
                 : "=r"(old) : "l"(p) : "memory");
    return old;
}

// Single kernel: grid (CHUNKS, PP), 64 threads; 2 points x 3 levels per thread.
// Loop is byte-identical to R6's proven-fast k_partial.
__global__ __launch_bounds__(64) void k_all(
    const float* __restrict__ pred0, const float* __restrict__ pred1,
    const float* __restrict__ pred2, const float* __restrict__ gt,
    float* __restrict__ out)
{
    __shared__ __align__(16) float sA[CM];
    __shared__ __align__(16) float sB[CM];
    __shared__ __align__(16) float sC[CM];
    __shared__ unsigned s_ticket;
    __shared__ float s_w[2];

    const int ch  = blockIdx.x;
    const int p   = blockIdx.y;
    const int tid = threadIdx.x;

    // Load gt chunk, precompute A=-2gx, B=-2gy, C=|g|^2  (128 pts by 64 threads)
    {
        const float2* gsrc = (const float2*)(gt + ((size_t)p * MM + (size_t)ch * CM) * 2);
        #pragma unroll
        for (int k = 0; k < 2; k++) {
            int m = tid + k * 64;
            float2 g = gsrc[m];
            sA[m] = -2.0f * g.x;
            sB[m] = -2.0f * g.y;
            sC[m] = fmaf(g.x, g.x, g.y * g.y);
        }
    }

    // Two points per thread, 3 levels each; coords are [...,1:] of last dim 3
    const int n0 = 2 * tid, n1 = 2 * tid + 1;
    const int ba = (p * NN + n0) * 3;
    const int bb = (p * NN + n1) * 3;
    const float x0a = pred0[ba + 1], y0a = pred0[ba + 2];
    const float x1a = pred1[ba + 1], y1a = pred1[ba + 2];
    const float x2a = pred2[ba + 1], y2a = pred2[ba + 2];
    const float x0b = pred0[bb + 1], y0b = pred0[bb + 2];
    const float x1b = pred1[bb + 1], y1b = pred1[bb + 2];
    const float x2b = pred2[bb + 1], y2b = pred2[bb + 2];
    __syncthreads();

    const u64 X0a = pack2(x0a), Y0a = pack2(y0a), X0b = pack2(x0b), Y0b = pack2(y0b);
    const u64 X1a = pack2(x1a), Y1a = pack2(y1a), X1b = pack2(x1b), Y1b = pack2(y1b);
    const u64 X2a = pack2(x2a), Y2a = pack2(y2a), X2b = pack2(x2b), Y2b = pack2(y2b);

    const float INF = __int_as_float(0x7f800000);
    float m0a0 = INF, m0a1 = INF, m0b0 = INF, m0b1 = INF;
    float m1a0 = INF, m1a1 = INF, m1b0 = INF, m1b1 = INF;
    float m2a0 = INF, m2a1 = INF, m2b0 = INF, m2b1 = INF;

    const ulonglong2* A2 = (const ulonglong2*)sA;   // plain derefs -> schedulable LDS.128
    const ulonglong2* B2 = (const ulonglong2*)sB;
    const ulonglong2* C2 = (const ulonglong2*)sC;

    #pragma unroll 8
    for (int i = 0; i < CM / 4; i++) {              // 4 gt points per iteration
        ulonglong2 av = A2[i], bv = B2[i], cv = C2[i];
        // level 0
        min2acc(m0a0, m0a1, fma2(Y0a, bv.x, fma2(X0a, av.x, cv.x)));
        min2acc(m0a0, m0a1, fma2(Y0a, bv.y, fma2(X0a, av.y, cv.y)));
        min2acc(m0b0, m0b1, fma2(Y0b, bv.x, fma2(X0b, av.x, cv.x)));
        min2acc(m0b0, m0b1, fma2(Y0b, bv.y, fma2(X0b, av.y, cv.y)));
        // level 1
        min2acc(m1a0, m1a1, fma2(Y1a, bv.x, fma2(X1a, av.x, cv.x)));
        min2acc(m1a0, m1a1, fma2(Y1a, bv.y, fma2(X1a, av.y, cv.y)));
        min2acc(m1b0, m1b1, fma2(Y1b, bv.x, fma2(X1b, av.x, cv.x)));
        min2acc(m1b0, m1b1, fma2(Y1b, bv.y, fma2(X1b, av.y, cv.y)));
        // level 2
        min2acc(m2a0, m2a1, fma2(Y2a, bv.x, fma2(X2a, av.x, cv.x)));
        min2acc(m2a0, m2a1, fma2(Y2a, bv.y, fma2(X2a, av.y, cv.y)));
        min2acc(m2b0, m2b1, fma2(Y2b, bv.x, fma2(X2b, av.x, cv.x)));
        min2acc(m2b0, m2b1, fma2(Y2b, bv.y, fma2(X2b, av.y, cv.y)));
    }

    const int pta = p * NN + n0;
    const int ptb = p * NN + n1;
    g_partial[ch][0 * LVL_STRIDE + pta] = fminf(m0a0, m0a1) + fmaf(x0a, x0a, y0a * y0a);
    g_partial[ch][0 * LVL_STRIDE + ptb] = fminf(m0b0, m0b1) + fmaf(x0b, x0b, y0b * y0b);
    g_partial[ch][1 * LVL_STRIDE + pta] = fminf(m1a0, m1a1) + fmaf(x1a, x1a, y1a * y1a);
    g_partial[ch][1 * LVL_STRIDE + ptb] = fminf(m1b0, m1b1) + fmaf(x1b, x1b, y1b * y1b);
    g_partial[ch][2 * LVL_STRIDE + pta] = fminf(m2a0, m2a1) + fmaf(x2a, x2a, y2a * y2a);
    g_partial[ch][2 * LVL_STRIDE + ptb] = fminf(m2b0, m2b1) + fmaf(x2b, x2b, y2b * y2b);

    // ---- per-polygon ticket: last of 8 chunk-CTAs combines polygon p ----
    __syncthreads();                         // all threads' STGs precede tid0's release
    if (tid == 0) s_ticket = atom_ticket(&g_cnt[p]);
    __syncthreads();                         // propagate tid0's acquire to the CTA
    if (s_ticket != CHUNKS - 1) return;

    // Combine 384 (level,point) slots with 64 threads: 6 slots, 48 independent L2 loads
    float acc = 0.0f;
    #pragma unroll
    for (int k = 0; k < 6; k++) {
        const int s = k * 64 + tid;          // slot in [0, 384)
        const int l = s >> 7;
        const int n = s & (NN - 1);
        const int idx = l * LVL_STRIDE + p * NN + n;
        float v = __ldcg(&g_partial[0][idx]);
        #pragma unroll
        for (int c = 1; c < CHUNKS; c++)
            v = fminf(v, __ldcg(&g_partial[c][idx]));
        const float w = (l == 0) ? W0 : ((l == 1) ? W1 : W2);
        acc = fmaf(w, sqrtf(fmaxf(v, 0.0f)), acc);
    }
    // deterministic reduce of 64 threads (2 warps)
    #pragma unroll
    for (int off = 16; off > 0; off >>= 1)
        acc += __shfl_xor_sync(0xffffffffu, acc, off);
    if ((tid & 31) == 0) s_w[tid >> 5] = acc;
    __syncthreads();

    if (tid == 0) {
        g_poly[p] = s_w[0] + s_w[1];         // tid0's own STG: covered by its release
        g_cnt[p] = 0;                        // reset for next graph replay
        s_ticket = atom_ticket(&g_cnt2);     // global ticket (release g_poly[p])
    }
    __syncthreads();
    if (s_ticket != PP - 1) return;

    if (tid == 0) g_cnt2 = 0;                // reset for next graph replay
    // ---- final: last combiner sums 128 polygon scalars (fixed order) ----
    float v2 = __ldcg(&g_poly[tid]) + __ldcg(&g_poly[tid + 64]);
    #pragma unroll
    for (int off = 16; off > 0; off >>= 1)
        v2 += __shfl_xor_sync(0xffffffffu, v2, off);
    if ((tid & 31) == 0) s_w[tid >> 5] = v2;
    __syncthreads();
    if (tid == 0) *out = s_w[0] + s_w[1];
}

extern "C" void kernel_launch(void* const* d_in, const int* in_sizes, int n_in,
                              void* d_out, int out_size)
{
    const float* pred0 = (const float*)d_in[0];
    const float* pred1 = (const float*)d_in[1];
    const float* pred2 = (const float*)d_in[2];
    const float* gt    = (const float*)d_in[3];

    dim3 grid(CHUNKS, PP);
    k_all<<<grid, 64>>>(pred0, pred1, pred2, gt, (float*)d_out);
}

// round 13
// speedup vs baseline: 1.3841x; 1.3841x over previous
#include <cuda_runtime.h>

// Problem constants
#define PP      128                 // polygons
#define NN      128                 // pred points per polygon per level
#define MM      1024                // gt points per polygon
#define H       8                   // gt slices per polygon
#define GPH     (MM/H)              // 128 gt per slice
#define NG      (GPH/4)             // 32 groups of 4 gt per slice
#define THREADS 512                 // = (NN/2) * H

// level weights / (3 * P * N)
#define W0 (0.2f/49152.0f)
#define W1 (0.3f/49152.0f)
#define W2 (0.5f/49152.0f)

typedef unsigned long long u64;

// Scratch (no allocations allowed)
__device__ float g_poly[PP];        // per-polygon weighted sums
__device__ int   g_cnt2;            // ticket (zero-init; winner resets)

// ---- packed f32x2 helpers (sm_103a). fma2 is pure (non-volatile): schedulable. ----
__device__ __forceinline__ u64 pack2(float x) {
    u64 r; asm("mov.b64 %0, {%1, %1};" : "=l"(r) : "f"(x)); return r;
}
__device__ __forceinline__ u64 fma2(u64 a, u64 b, u64 c) {
    u64 d; asm("fma.rn.f32x2 %0, %1, %2, %3;" : "=l"(d) : "l"(a), "l"(b), "l"(c)); return d;
}
__device__ __forceinline__ void min2acc(float& m0, float& m1, u64 t) {
    float2 f = *reinterpret_cast<float2*>(&t);
    m0 = fminf(m0, f.x);
    m1 = fminf(m1, f.y);
}

// Single kernel: CTA = polygon. 512 threads = 64 point-pairs x 8 gt-slices.
// Loop adds: per-warp staggered ring start + manual 2-stage LDS prefetch.
__global__ __launch_bounds__(THREADS) void k_all(
    const float* __restrict__ pred0, const float* __restrict__ pred1,
    const float* __restrict__ pred2, const float* __restrict__ gt,
    float* __restrict__ out)
{
    __shared__ __align__(16) float sA[MM];
    __shared__ __align__(16) float sB[MM];
    __shared__ __align__(16) float sC[MM];
    __shared__ float s_half[3 * H * NN];   // [level][slice][point]
    __shared__ float s_warp[16];
    __shared__ int   s_final;

    const int p = blockIdx.x;
    const int t = threadIdx.x;

    const int tn = t & 63;                 // point-pair index (points 2tn, 2tn+1)
    const int h  = t >> 6;                 // gt slice 0..7
    const int n0 = 2 * tn, n1 = 2 * tn + 1;

    // prologue global loads first (overlap with smem fill)
    const int ba = (p * NN + n0) * 3;      // coords are [...,1:] of last dim 3
    const float x0a = pred0[ba + 1], y0a = pred0[ba + 2];
    const float x0b = pred0[ba + 4], y0b = pred0[ba + 5];
    const float x1a = pred1[ba + 1], y1a = pred1[ba + 2];
    const float x1b = pred1[ba + 4], y1b = pred1[ba + 5];
    const float x2a = pred2[ba + 1], y2a = pred2[ba + 2];
    const float x2b = pred2[ba + 4], y2b = pred2[ba + 5];

    // ---- load ALL gt of this polygon; precompute A=-2gx, B=-2gy, C=|g|^2 ----
    {
        const float2* gsrc = (const float2*)(gt + (size_t)p * MM * 2);
        #pragma unroll
        for (int k = 0; k < 2; k++) {
            int m = t + k * THREADS;
            float2 g = gsrc[m];
            sA[m] = -2.0f * g.x;
            sB[m] = -2.0f * g.y;
            sC[m] = fmaf(g.x, g.x, g.y * g.y);
        }
    }
    __syncthreads();

    const u64 X0a = pack2(x0a), Y0a = pack2(y0a), X0b = pack2(x0b), Y0b = pack2(y0b);
    const u64 X1a = pack2(x1a), Y1a = pack2(y1a), X1b = pack2(x1b), Y1b = pack2(y1b);
    const u64 X2a = pack2(x2a), Y2a = pack2(y2a), X2b = pack2(x2b), Y2b = pack2(y2b);

    const float INF = __int_as_float(0x7f800000);
    float m0a0 = INF, m0a1 = INF, m0b0 = INF, m0b1 = INF;
    float m1a0 = INF, m1a1 = INF, m1b0 = INF, m1b1 = INF;
    float m2a0 = INF, m2a1 = INF, m2b0 = INF, m2b1 = INF;

    const ulonglong2* A2 = (const ulonglong2*)(sA + h * GPH);  // schedulable LDS.128
    const ulonglong2* B2 = (const ulonglong2*)(sB + h * GPH);
    const ulonglong2* C2 = (const ulonglong2*)(sC + h * GPH);

    // per-warp staggered ring start: de-phases the 16 warps' LDS bursts
    const int woff = ((t >> 5) * 4) & (NG - 1);

    // manual 2-stage pipeline: prefetch group k+1 while computing group k
    int idx0 = woff;
    ulonglong2 av = A2[idx0], bv = B2[idx0], cv = C2[idx0];

    #pragma unroll 4
    for (int k = 0; k < NG; k++) {
        const int jn = (k + 1 + woff) & (NG - 1);  // next group (wraps; k=NG-1 value unused)
        ulonglong2 an = A2[jn], bn = B2[jn], cn = C2[jn];
        // level 0, points a & b
        min2acc(m0a0, m0a1, fma2(Y0a, bv.x, fma2(X0a, av.x, cv.x)));
        min2acc(m0a0, m0a1, fma2(Y0a, bv.y, fma2(X0a, av.y, cv.y)));
        min2acc(m0b0, m0b1, fma2(Y0b, bv.x, fma2(X0b, av.x, cv.x)));
        min2acc(m0b0, m0b1, fma2(Y0b, bv.y, fma2(X0b, av.y, cv.y)));
        // level 1
        min2acc(m1a0, m1a1, fma2(Y1a, bv.x, fma2(X1a, av.x, cv.x)));
        min2acc(m1a0, m1a1, fma2(Y1a, bv.y, fma2(X1a, av.y, cv.y)));
        min2acc(m1b0, m1b1, fma2(Y1b, bv.x, fma2(X1b, av.x, cv.x)));
        min2acc(m1b0, m1b1, fma2(Y1b, bv.y, fma2(X1b, av.y, cv.y)));
        // level 2
        min2acc(m2a0, m2a1, fma2(Y2a, bv.x, fma2(X2a, av.x, cv.x)));
        min2acc(m2a0, m2a1, fma2(Y2a, bv.y, fma2(X2a, av.y, cv.y)));
        min2acc(m2b0, m2b1, fma2(Y2b, bv.x, fma2(X2b, av.x, cv.x)));
        min2acc(m2b0, m2b1, fma2(Y2b, bv.y, fma2(X2b, av.y, cv.y)));
        av = an; bv = bn; cv = cn;
    }

    // per-(level, slice, point) partial min d^2
    s_half[(0 * H + h) * NN + n0] = fminf(m0a0, m0a1) + fmaf(x0a, x0a, y0a * y0a);
    s_half[(0 * H + h) * NN + n1] = fminf(m0b0, m0b1) + fmaf(x0b, x0b, y0b * y0b);
    s_half[(1 * H + h) * NN + n0] = fminf(m1a0, m1a1) + fmaf(x1a, x1a, y1a * y1a);
    s_half[(1 * H + h) * NN + n1] = fminf(m1b0, m1b1) + fmaf(x1b, x1b, y1b * y1b);
    s_half[(2 * H + h) * NN + n0] = fminf(m2a0, m2a1) + fmaf(x2a, x2a, y2a * y2a);
    s_half[(2 * H + h) * NN + n1] = fminf(m2b0, m2b1) + fmaf(x2b, x2b, y2b * y2b);
    __syncthreads();

    // ---- combine slices: threads 0..383 own (level l = t>>7, point nn) ----
    float val = 0.0f;
    if (t < 3 * NN) {
        const int l  = t >> 7;
        const int nn = t & (NN - 1);
        const float* sh = s_half + l * H * NN + nn;
        float v = fminf(fminf(fminf(sh[0 * NN], sh[1 * NN]),
                              fminf(sh[2 * NN], sh[3 * NN])),
                        fminf(fminf(sh[4 * NN], sh[5 * NN]),
                              fminf(sh[6 * NN], sh[7 * NN])));
        const float w = (l == 0) ? W0 : ((l == 1) ? W1 : W2);
        val = w * sqrtf(fmaxf(v, 0.0f));
    }
    // deterministic fixed-tree reduction
    #pragma unroll
    for (int off = 16; off > 0; off >>= 1)
        val += __shfl_xor_sync(0xffffffffu, val, off);
    if ((t & 31) == 0) s_warp[t >> 5] = val;
    __syncthreads();

    if (t == 0) {
        float s = 0.0f;
        #pragma unroll
        for (int i = 0; i < 12; i++) s += s_warp[i];   // warps >=12 contribute 0
        g_poly[p] = s;
        __threadfence();                   // release g_poly[p] (1 per CTA, 128 total)
        int tk = atomicAdd(&g_cnt2, 1);
        s_final = (tk == PP - 1);
        if (s_final) g_cnt2 = 0;           // reset for next graph replay
    }
    __syncthreads();
    if (!s_final) return;                  // uniform across CTA

    // ---- last CTA: sum the 128 polygon scalars (fixed order) ----
    __threadfence();                       // acquire other CTAs' g_poly writes
    float v2 = (t < PP) ? __ldcg(&g_poly[t]) : 0.0f;
    #pragma unroll
    for (int off = 16; off > 0; off >>= 1)
        v2 += __shfl_xor_sync(0xffffffffu, v2, off);
    if ((t & 31) == 0) s_warp[t >> 5] = v2;
    __syncthreads();
    if (t == 0) {
        float s = 0.0f;
        #pragma unroll
        for (int i = 0; i < 4; i++) s += s_warp[i];    // only first 4 warps held data
        *out = s;
    }
}

extern "C" void kernel_launch(void* const* d_in, const int* in_sizes, int n_in,
                              void* d_out, int out_size)
{
    const float* pred0 = (const float*)d_in[0];
    const float* pred1 = (const float*)d_in[1];
    const float* pred2 = (const float*)d_in[2];
    const float* gt    = (const float*)d_in[3];

    k_all<<<PP, THREADS>>>(pred0, pred1, pred2, gt, (float*)d_out);
}

// round 14
// speedup vs baseline: 1.4047x; 1.0148x over previous
#include <cuda_runtime.h>

// Problem constants
#define PP      128                 // polygons
#define NN      128                 // pred points per polygon per level
#define MM      1024                // gt points per polygon
#define H       4                   // gt slices per polygon
#define GPH     (MM/H)              // 256 gt per slice
#define THREADS 512                 // = NN * H

// level weights / (3 * P * N)
#define W0 (0.2f/49152.0f)
#define W1 (0.3f/49152.0f)
#define W2 (0.5f/49152.0f)

// Scratch (no allocations allowed)
__device__ float g_poly[PP];        // per-polygon weighted sums
__device__ int   g_cnt2;            // ticket (zero-init; winner resets)

// Single kernel: CTA = polygon. 512 threads = 128 points x 4 gt-slices.
// ALL-SCALAR math: no fma.f32x2 anywhere (suspected hidden-pipe bottleneck).
__global__ __launch_bounds__(THREADS) void k_all(
    const float* __restrict__ pred0, const float* __restrict__ pred1,
    const float* __restrict__ pred2, const float* __restrict__ gt,
    float* __restrict__ out)
{
    __shared__ __align__(16) float sA[MM];
    __shared__ __align__(16) float sB[MM];
    __shared__ __align__(16) float sC[MM];
    __shared__ float s_half[3 * H * NN];   // [level][slice][point]
    __shared__ float s_warp[16];
    __shared__ int   s_final;

    const int p = blockIdx.x;
    const int t = threadIdx.x;

    // ---- load ALL gt of this polygon; precompute A=-2gx, B=-2gy, C=|g|^2 ----
    {
        const float2* gsrc = (const float2*)(gt + (size_t)p * MM * 2);
        #pragma unroll
        for (int k = 0; k < 2; k++) {
            int m = t + k * THREADS;
            float2 g = gsrc[m];
            sA[m] = -2.0f * g.x;
            sB[m] = -2.0f * g.y;
            sC[m] = fmaf(g.x, g.x, g.y * g.y);
        }
    }

    const int n = t & (NN - 1);            // point index
    const int h = t >> 7;                  // gt slice 0..3
    const int base = (p * NN + n) * 3;     // coords are [...,1:] of last dim 3
    const float x0 = pred0[base + 1], y0 = pred0[base + 2];
    const float x1 = pred1[base + 1], y1 = pred1[base + 2];
    const float x2 = pred2[base + 1], y2 = pred2[base + 2];
    __syncthreads();

    const float INF = __int_as_float(0x7f800000);
    // 2 accumulators per level (even/odd gt) for FMNMX-chain ILP
    float m0e = INF, m0o = INF, m1e = INF, m1o = INF, m2e = INF, m2o = INF;

    const float4* A4 = (const float4*)(sA + h * GPH);  // LDS.128, warp-broadcast
    const float4* B4 = (const float4*)(sB + h * GPH);
    const float4* C4 = (const float4*)(sC + h * GPH);

    #pragma unroll 8
    for (int i = 0; i < GPH / 4; i++) {    // 4 gt per iter, 64 iters
        float4 a = A4[i], b = B4[i], c = C4[i];
        float u;
        // gt j=0
        u = fmaf(y0, b.x, fmaf(x0, a.x, c.x)); m0e = fminf(m0e, u);
        u = fmaf(y1, b.x, fmaf(x1, a.x, c.x)); m1e = fminf(m1e, u);
        u = fmaf(y2, b.x, fmaf(x2, a.x, c.x)); m2e = fminf(m2e, u);
        // gt j=1
        u = fmaf(y0, b.y, fmaf(x0, a.y, c.y)); m0o = fminf(m0o, u);
        u = fmaf(y1, b.y, fmaf(x1, a.y, c.y)); m1o = fminf(m1o, u);
        u = fmaf(y2, b.y, fmaf(x2, a.y, c.y)); m2o = fminf(m2o, u);
        // gt j=2
        u = fmaf(y0, b.z, fmaf(x0, a.z, c.z)); m0e = fminf(m0e, u);
        u = fmaf(y1, b.z, fmaf(x1, a.z, c.z)); m1e = fminf(m1e, u);
        u = fmaf(y2, b.z, fmaf(x2, a.z, c.z)); m2e = fminf(m2e, u);
        // gt j=3
        u = fmaf(y0, b.w, fmaf(x0, a.w, c.w)); m0o = fminf(m0o, u);
        u = fmaf(y1, b.w, fmaf(x1, a.w, c.w)); m1o = fminf(m1o, u);
        u = fmaf(y2, b.w, fmaf(x2, a.w, c.w)); m2o = fminf(m2o, u);
    }

    // per-(level, slice, point) partial min d^2
    s_half[(0 * H + h) * NN + n] = fminf(m0e, m0o) + fmaf(x0, x0, y0 * y0);
    s_half[(1 * H + h) * NN + n] = fminf(m1e, m1o) + fmaf(x1, x1, y1 * y1);
    s_half[(2 * H + h) * NN + n] = fminf(m2e, m2o) + fmaf(x2, x2, y2 * y2);
    __syncthreads();

    // ---- combine slices: threads 0..383 own (level l = t>>7, point nn) ----
    float val = 0.0f;
    if (t < 3 * NN) {
        const int l  = t >> 7;
        const int nn = t & (NN - 1);
        const float* sh = s_half + l * H * NN + nn;
        float v = fminf(fminf(sh[0 * NN], sh[1 * NN]),
                        fminf(sh[2 * NN], sh[3 * NN]));
        const float w = (l == 0) ? W0 : ((l == 1) ? W1 : W2);
        val = w * sqrtf(fmaxf(v, 0.0f));
    }
    // deterministic fixed-tree reduction
    #pragma unroll
    for (int off = 16; off > 0; off >>= 1)
        val += __shfl_xor_sync(0xffffffffu, val, off);
    if ((t & 31) == 0) s_warp[t >> 5] = val;
    __syncthreads();

    if (t == 0) {
        float s = 0.0f;
        #pragma unroll
        for (int i = 0; i < 12; i++) s += s_warp[i];   // warps >=12 contribute 0
        g_poly[p] = s;
        __threadfence();                   // release g_poly[p] (1 per CTA, 128 total)
        int tk = atomicAdd(&g_cnt2, 1);
        s_final = (tk == PP - 1);
        if (s_final) g_cnt2 = 0;           // reset for next graph replay
    }
    __syncthreads();
    if (!s_final) return;                  // uniform across CTA

    // ---- last CTA: sum the 128 polygon scalars (fixed order) ----
    __threadfence();                       // acquire other CTAs' g_poly writes
    float v2 = (t < PP) ? __ldcg(&g_poly[t]) : 0.0f;
    #pragma unroll
    for (int off = 16; off > 0; off >>= 1)
        v2 += __shfl_xor_sync(0xffffffffu, v2, off);
    if ((t & 31) == 0) s_warp[t >> 5] = v2;
    __syncthreads();
    if (t == 0) {
        float s = 0.0f;
        #pragma unroll
        for (int i = 0; i < 4; i++) s += s_warp[i];    // only first 4 warps held data
        *out = s;
    }
}

extern "C" void kernel_launch(void* const* d_in, const int* in_sizes, int n_in,
                              void* d_out, int out_size)
{
    const float* pred0 = (const float*)d_in[0];
    const float* pred1 = (const float*)d_in[1];
    const float* pred2 = (const float*)d_in[2];
    const float* gt    = (const float*)d_in[3];

    k_all<<<PP, THREADS>>>(pred0, pred1, pred2, gt, (float*)d_out);
}

// round 15
// speedup vs baseline: 1.6617x; 1.1830x over previous
#include <cuda_runtime.h>

// Problem constants
#define PP      128                 // polygons
#define NN      128                 // pred points per polygon per level
#define MM      1024                // gt points per polygon
#define H       8                   // gt slices per polygon
#define GPH     (MM/H)              // 128 gt per slice
#define NG      (GPH/4)             // 32 groups of 4 gt per slice
#define THREADS 512                 // = (NN/2) * H

// level weights / (3 * P * N)
#define W0 (0.2f/49152.0f)
#define W1 (0.3f/49152.0f)
#define W2 (0.5f/49152.0f)

typedef unsigned long long u64;

// Scratch (no allocations allowed)
__device__ float g_poly[PP];        // per-polygon weighted sums
__device__ int   g_cnt2;            // ticket (zero-init; winner resets)

// ---- packed f32x2 helpers (sm_103a). fma2 is pure (non-volatile): schedulable. ----
__device__ __forceinline__ u64 pack2(float x) {
    u64 r; asm("mov.b64 %0, {%1, %1};" : "=l"(r) : "f"(x)); return r;
}
__device__ __forceinline__ u64 fma2(u64 a, u64 b, u64 c) {
    u64 d; asm("fma.rn.f32x2 %0, %1, %2, %3;" : "=l"(d) : "l"(a), "l"(b), "l"(c)); return d;
}
__device__ __forceinline__ void min2acc(float& m0, float& m1, u64 t) {
    float2 f = *reinterpret_cast<float2*>(&t);
    m0 = fminf(m0, f.x);
    m1 = fminf(m1, f.y);
}

// the 12-candidate-pair compute block on one (av,bv,cv) group
#define COMPUTE_GROUP(av, bv, cv)                                        \
    do {                                                                 \
        min2acc(m0a0, m0a1, fma2(Y0a, (bv).x, fma2(X0a, (av).x, (cv).x))); \
        min2acc(m0a0, m0a1, fma2(Y0a, (bv).y, fma2(X0a, (av).y, (cv).y))); \
        min2acc(m0b0, m0b1, fma2(Y0b, (bv).x, fma2(X0b, (av).x, (cv).x))); \
        min2acc(m0b0, m0b1, fma2(Y0b, (bv).y, fma2(X0b, (av).y, (cv).y))); \
        min2acc(m1a0, m1a1, fma2(Y1a, (bv).x, fma2(X1a, (av).x, (cv).x))); \
        min2acc(m1a0, m1a1, fma2(Y1a, (bv).y, fma2(X1a, (av).y, (cv).y))); \
        min2acc(m1b0, m1b1, fma2(Y1b, (bv).x, fma2(X1b, (av).x, (cv).x))); \
        min2acc(m1b0, m1b1, fma2(Y1b, (bv).y, fma2(X1b, (av).y, (cv).y))); \
        min2acc(m2a0, m2a1, fma2(Y2a, (bv).x, fma2(X2a, (av).x, (cv).x))); \
        min2acc(m2a0, m2a1, fma2(Y2a, (bv).y, fma2(X2a, (av).y, (cv).y))); \
        min2acc(m2b0, m2b1, fma2(Y2b, (bv).x, fma2(X2b, (av).x, (cv).x))); \
        min2acc(m2b0, m2b1, fma2(Y2b, (bv).y, fma2(X2b, (av).y, (cv).y))); \
    } while (0)

// Single kernel: CTA = polygon. 512 threads = 64 point-pairs x 8 gt-slices.
// Loop = R11 + linear 2-stage LDS prefetch pipeline (no ring, no index math).
__global__ __launch_bounds__(THREADS, 1) void k_all(
    const float* __restrict__ pred0, const float* __restrict__ pred1,
    const float* __restrict__ pred2, const float* __restrict__ gt,
    float* __restrict__ out)
{
    __shared__ __align__(16) float sA[MM];
    __shared__ __align__(16) float sB[MM];
    __shared__ __align__(16) float sC[MM];
    __shared__ float s_half[3 * H * NN];   // [level][slice][point]
    __shared__ float s_warp[16];
    __shared__ int   s_final;

    const int p = blockIdx.x;
    const int t = threadIdx.x;

    const int tn = t & 63;                 // point-pair index (points 2tn, 2tn+1)
    const int h  = t >> 6;                 // gt slice 0..7
    const int n0 = 2 * tn, n1 = 2 * tn + 1;

    // prologue global loads first (overlap with smem fill)
    const int ba = (p * NN + n0) * 3;      // coords are [...,1:] of last dim 3
    const float x0a = pred0[ba + 1], y0a = pred0[ba + 2];
    const float x0b = pred0[ba + 4], y0b = pred0[ba + 5];
    const float x1a = pred1[ba + 1], y1a = pred1[ba + 2];
    const float x1b = pred1[ba + 4], y1b = pred1[ba + 5];
    const float x2a = pred2[ba + 1], y2a = pred2[ba + 2];
    const float x2b = pred2[ba + 4], y2b = pred2[ba + 5];

    // ---- load ALL gt of this polygon; precompute A=-2gx, B=-2gy, C=|g|^2 ----
    {
        const float2* gsrc = (const float2*)(gt + (size_t)p * MM * 2);
        #pragma unroll
        for (int k = 0; k < 2; k++) {
            int m = t + k * THREADS;
            float2 g = gsrc[m];
            sA[m] = -2.0f * g.x;
            sB[m] = -2.0f * g.y;
            sC[m] = fmaf(g.x, g.x, g.y * g.y);
        }
    }
    __syncthreads();

    const u64 X0a = pack2(x0a), Y0a = pack2(y0a), X0b = pack2(x0b), Y0b = pack2(y0b);
    const u64 X1a = pack2(x1a), Y1a = pack2(y1a), X1b = pack2(x1b), Y1b = pack2(y1b);
    const u64 X2a = pack2(x2a), Y2a = pack2(y2a), X2b = pack2(x2b), Y2b = pack2(y2b);

    const float INF = __int_as_float(0x7f800000);
    float m0a0 = INF, m0a1 = INF, m0b0 = INF, m0b1 = INF;
    float m1a0 = INF, m1a1 = INF, m1b0 = INF, m1b1 = INF;
    float m2a0 = INF, m2a1 = INF, m2b0 = INF, m2b1 = INF;

    const ulonglong2* A2 = (const ulonglong2*)(sA + h * GPH);
    const ulonglong2* B2 = (const ulonglong2*)(sB + h * GPH);
    const ulonglong2* C2 = (const ulonglong2*)(sC + h * GPH);

    // 2-stage linear pipeline: group i+1's LDS issues before group i's compute
    ulonglong2 av = A2[0], bv = B2[0], cv = C2[0];
    #pragma unroll 4
    for (int i = 0; i < NG - 1; i++) {
        ulonglong2 an = A2[i + 1], bn = B2[i + 1], cn = C2[i + 1];
        COMPUTE_GROUP(av, bv, cv);
        av = an; bv = bn; cv = cn;
    }
    COMPUTE_GROUP(av, bv, cv);             // last group, already in registers

    // per-(level, slice, point) partial min d^2
    s_half[(0 * H + h) * NN + n0] = fminf(m0a0, m0a1) + fmaf(x0a, x0a, y0a * y0a);
    s_half[(0 * H + h) * NN + n1] = fminf(m0b0, m0b1) + fmaf(x0b, x0b, y0b * y0b);
    s_half[(1 * H + h) * NN + n0] = fminf(m1a0, m1a1) + fmaf(x1a, x1a, y1a * y1a);
    s_half[(1 * H + h) * NN + n1] = fminf(m1b0, m1b1) + fmaf(x1b, x1b, y1b * y1b);
    s_half[(2 * H + h) * NN + n0] = fminf(m2a0, m2a1) + fmaf(x2a, x2a, y2a * y2a);
    s_half[(2 * H + h) * NN + n1] = fminf(m2b0, m2b1) + fmaf(x2b, x2b, y2b * y2b);
    __syncthreads();

    // ---- combine slices: threads 0..383 own (level l = t>>7, point nn) ----
    float val = 0.0f;
    if (t < 3 * NN) {
        const int l  = t >> 7;
        const int nn = t & (NN - 1);
        const float* sh = s_half + l * H * NN + nn;
        float v = fminf(fminf(fminf(sh[0 * NN], sh[1 * NN]),
                              fminf(sh[2 * NN], sh[3 * NN])),
                        fminf(fminf(sh[4 * NN], sh[5 * NN]),
                              fminf(sh[6 * NN], sh[7 * NN])));
        const float w = (l == 0) ? W0 : ((l == 1) ? W1 : W2);
        val = w * sqrtf(fmaxf(v, 0.0f));
    }
    // deterministic fixed-tree reduction
    #pragma unroll
    for (int off = 16; off > 0; off >>= 1)
        val += __shfl_xor_sync(0xffffffffu, val, off);
    if ((t & 31) == 0) s_warp[t >> 5] = val;
    __syncthreads();

    if (t == 0) {
        float s = 0.0f;
        #pragma unroll
        for (int i = 0; i < 12; i++) s += s_warp[i];   // warps >=12 contribute 0
        g_poly[p] = s;
        __threadfence();                   // release g_poly[p] (1 per CTA, 128 total)
        int tk = atomicAdd(&g_cnt2, 1);
        s_final = (tk == PP - 1);
        if (s_final) g_cnt2 = 0;           // reset for next graph replay
    }
    __syncthreads();
    if (!s_final) return;                  // uniform across CTA

    // ---- last CTA: sum the 128 polygon scalars (fixed order) ----
    __threadfence();                       // acquire other CTAs' g_poly writes
    float v2 = (t < PP) ? __ldcg(&g_poly[t]) : 0.0f;
    #pragma unroll
    for (int off = 16; off > 0; off >>= 1)
        v2 += __shfl_xor_sync(0xffffffffu, v2, off);
    if ((t & 31) == 0) s_warp[t >> 5] = v2;
    __syncthreads();
    if (t == 0) {
        float s = 0.0f;
        #pragma unroll
        for (int i = 0; i < 4; i++) s += s_warp[i];    // only first 4 warps held data
        *out = s;
    }
}

extern "C" void kernel_launch(void* const* d_in, const int* in_sizes, int n_in,
                              void* d_out, int out_size)
{
    const float* pred0 = (const float*)d_in[0];
    const float* pred1 = (const float*)d_in[1];
    const float* pred2 = (const float*)d_in[2];
    const float* gt    = (const float*)d_in[3];

    k_all<<<PP, THREADS>>>(pred0, pred1, pred2, gt, (float*)d_out);
}